// round 1
// baseline (speedup 1.0000x reference)
#include <cuda_runtime.h>
#include <cstdint>

#define NN 100000
#define NE 800000
#define F  128
#define FG 32   // float4 groups per feature row

// ---------------- scratch (static device globals; no allocs allowed) --------
__device__ float    g_outdeg[NN];
__device__ float    g_indeg[NN];
__device__ float    g_hsum [(size_t)NN * F];
__device__ float    g_hprod[(size_t)NN * F];
__device__ float    g_logsum[(size_t)NN * F];
__device__ unsigned g_sign [(size_t)NN * FG];

// vector reduction: red.global.add.v4.f32 (sm_90+)
__device__ __forceinline__ void red_add_f4(float* p, float4 v) {
    asm volatile("red.global.add.v4.f32 [%0], {%1,%2,%3,%4};"
                 :: "l"(p), "f"(v.x), "f"(v.y), "f"(v.z), "f"(v.w)
                 : "memory");
}

// ---------------- K1: degrees ----------------
__global__ void k_degree(const int* __restrict__ src, const int* __restrict__ dst) {
    int e = blockIdx.x * blockDim.x + threadIdx.x;
    if (e < NE) {
        atomicAdd(&g_outdeg[src[e]], 1.0f);
        atomicAdd(&g_indeg [dst[e]], 1.0f);
    }
}

// ---------------- K2: fused dual node GEMM --------------------------------
// h_sum  = (feat * outdeg^-1/2) @ w1                  [N,128]
// h_prod = tanh([feat_src, 1] @ w2)                   [N,128]
// Block: 64 nodes x 128 outs, 256 threads, 8x4 reg tile per thread, K-tile 32.
__global__ __launch_bounds__(256) void k_node(const float* __restrict__ feat,
                                              const float* __restrict__ w1,
                                              const float* __restrict__ w2) {
    __shared__ float sFt[32][65];   // transposed feat tile [k][node]
    __shared__ float sW1[32][128];
    __shared__ float sW2[32][128];
    __shared__ float sR[64];

    const int t  = threadIdx.x;
    const int n0 = blockIdx.x * 64;

    if (t < 64) {
        int n = n0 + t;
        float d = (n < NN) ? g_outdeg[n] : 1.0f;
        sR[t] = rsqrtf(fmaxf(d, 1.0f));
    }
    __syncthreads();

    float a1[8][4], a2[8][4];
    #pragma unroll
    for (int i = 0; i < 8; i++)
        #pragma unroll
        for (int j = 0; j < 4; j++) { a1[i][j] = 0.f; a2[i][j] = 0.f; }

    const int tx = t & 31, ty = t >> 5;
    const int c0 = tx * 4, r0 = ty * 8;

    for (int k0 = 0; k0 < 128; k0 += 32) {
        // feat tile: 64 rows x 32 k  -> transposed, scaled
        #pragma unroll
        for (int q = 0; q < 2; q++) {
            int idx = t * 2 + q;
            int row = idx >> 3;
            int kc  = (idx & 7) * 4;
            int n   = n0 + row; if (n >= NN) n = NN - 1;
            float4 fv = *reinterpret_cast<const float4*>(&feat[(size_t)n * F + k0 + kc]);
            float r = sR[row];
            sFt[kc + 0][row] = fv.x * r;
            sFt[kc + 1][row] = fv.y * r;
            sFt[kc + 2][row] = fv.z * r;
            sFt[kc + 3][row] = fv.w * r;
        }
        // weight tiles: 32 rows x 128 cols each
        #pragma unroll
        for (int q = 0; q < 4; q++) {
            int idx = t * 4 + q;
            int row = idx >> 5;
            int cc  = (idx & 31) * 4;
            *reinterpret_cast<float4*>(&sW1[row][cc]) =
                *reinterpret_cast<const float4*>(&w1[(size_t)(k0 + row) * F + cc]);
            *reinterpret_cast<float4*>(&sW2[row][cc]) =
                *reinterpret_cast<const float4*>(&w2[(size_t)(k0 + row) * F + cc]);
        }
        __syncthreads();

        #pragma unroll 8
        for (int kk = 0; kk < 32; kk++) {
            float4 wa = *reinterpret_cast<float4*>(&sW1[kk][c0]);
            float4 wb = *reinterpret_cast<float4*>(&sW2[kk][c0]);
            #pragma unroll
            for (int i = 0; i < 8; i++) {
                float f = sFt[kk][r0 + i];
                a1[i][0] += f * wa.x; a1[i][1] += f * wa.y;
                a1[i][2] += f * wa.z; a1[i][3] += f * wa.w;
                a2[i][0] += f * wb.x; a2[i][1] += f * wb.y;
                a2[i][2] += f * wb.z; a2[i][3] += f * wb.w;
            }
        }
        __syncthreads();
    }

    // bias row of w2 (row 128) multiplies the constant 1 appended to feat
    float4 bias = *reinterpret_cast<const float4*>(&w2[(size_t)128 * F + c0]);

    #pragma unroll
    for (int i = 0; i < 8; i++) {
        int n = n0 + r0 + i;
        if (n < NN) {
            float4 o1 = make_float4(a1[i][0], a1[i][1], a1[i][2], a1[i][3]);
            *reinterpret_cast<float4*>(&g_hsum[(size_t)n * F + c0]) = o1;
            float4 o2;
            o2.x = tanhf(a2[i][0] + bias.x);
            o2.y = tanhf(a2[i][1] + bias.y);
            o2.z = tanhf(a2[i][2] + bias.z);
            o2.w = tanhf(a2[i][3] + bias.w);
            *reinterpret_cast<float4*>(&g_hprod[(size_t)n * F + c0]) = o2;
        }
    }
}

// ---------------- K3: edge scatter -----------------------------------------
// one warp per edge, lane g handles features [4g, 4g+3]
__global__ __launch_bounds__(256) void k_edge(const int* __restrict__ src,
                                              const int* __restrict__ dst,
                                              const int* __restrict__ eattr,
                                              const float* __restrict__ bond,
                                              float* __restrict__ out) {
    int e = blockIdx.x * 8 + (threadIdx.x >> 5);
    if (e >= NE) return;
    int g = threadIdx.x & 31;

    int s = __ldg(&src[e]);
    int d = __ldg(&dst[e]);
    int a = __ldg(&eattr[e]);

    float4 ew = __ldg(reinterpret_cast<const float4*>(bond) + (size_t)a * FG + g);
    float4 hs = __ldg(reinterpret_cast<const float4*>(g_hsum)  + (size_t)s * FG + g);
    float4 hp = __ldg(reinterpret_cast<const float4*>(g_hprod) + (size_t)s * FG + g);

    // segment_sum path -> accumulate directly into d_out
    float4 ms = make_float4(hs.x * ew.x, hs.y * ew.y, hs.z * ew.z, hs.w * ew.w);
    red_add_f4(out + (size_t)d * F + g * 4, ms);

    // segment_prod path -> log magnitude + sign parity
    float4 mp = make_float4(hp.x * ew.x, hp.y * ew.y, hp.z * ew.z, hp.w * ew.w);
    float4 lg;
    lg.x = __logf(fabsf(mp.x));
    lg.y = __logf(fabsf(mp.y));
    lg.z = __logf(fabsf(mp.z));
    lg.w = __logf(fabsf(mp.w));
    red_add_f4(&g_logsum[(size_t)d * F + g * 4], lg);

    unsigned m =  ((__float_as_uint(mp.x) >> 31) & 1u)
               | (((__float_as_uint(mp.y) >> 31) & 1u) << 1)
               | (((__float_as_uint(mp.z) >> 31) & 1u) << 2)
               | (((__float_as_uint(mp.w) >> 31) & 1u) << 3);
    if (m) atomicXor(&g_sign[(size_t)d * FG + g], m);
}

// ---------------- K4: final GEMM + epilogue ---------------------------------
// hp = sign * exp(logsum); out = (hs + hp @ v) * indeg^-1/2
__global__ __launch_bounds__(256) void k_final(const float* __restrict__ v,
                                               float* __restrict__ out) {
    __shared__ float sHt[32][65];
    __shared__ float sV[32][128];

    const int t  = threadIdx.x;
    const int n0 = blockIdx.x * 64;

    float acc[8][4];
    #pragma unroll
    for (int i = 0; i < 8; i++)
        #pragma unroll
        for (int j = 0; j < 4; j++) acc[i][j] = 0.f;

    const int tx = t & 31, ty = t >> 5;
    const int c0 = tx * 4, r0 = ty * 8;

    for (int k0 = 0; k0 < 128; k0 += 32) {
        #pragma unroll
        for (int q = 0; q < 2; q++) {
            int idx = t * 2 + q;
            int row = idx >> 3;
            int kc  = (idx & 7) * 4;
            int n   = n0 + row; if (n >= NN) n = NN - 1;
            float4 lv = *reinterpret_cast<const float4*>(&g_logsum[(size_t)n * F + k0 + kc]);
            unsigned sg = g_sign[(size_t)n * FG + ((k0 + kc) >> 2)];
            float p0 = __expf(lv.x); if (sg & 1u) p0 = -p0;
            float p1 = __expf(lv.y); if (sg & 2u) p1 = -p1;
            float p2 = __expf(lv.z); if (sg & 4u) p2 = -p2;
            float p3 = __expf(lv.w); if (sg & 8u) p3 = -p3;
            sHt[kc + 0][row] = p0;
            sHt[kc + 1][row] = p1;
            sHt[kc + 2][row] = p2;
            sHt[kc + 3][row] = p3;
        }
        #pragma unroll
        for (int q = 0; q < 4; q++) {
            int idx = t * 4 + q;
            int row = idx >> 5;
            int cc  = (idx & 31) * 4;
            *reinterpret_cast<float4*>(&sV[row][cc]) =
                *reinterpret_cast<const float4*>(&v[(size_t)(k0 + row) * F + cc]);
        }
        __syncthreads();

        #pragma unroll 8
        for (int kk = 0; kk < 32; kk++) {
            float4 wv = *reinterpret_cast<float4*>(&sV[kk][c0]);
            #pragma unroll
            for (int i = 0; i < 8; i++) {
                float h = sHt[kk][r0 + i];
                acc[i][0] += h * wv.x; acc[i][1] += h * wv.y;
                acc[i][2] += h * wv.z; acc[i][3] += h * wv.w;
            }
        }
        __syncthreads();
    }

    #pragma unroll
    for (int i = 0; i < 8; i++) {
        int n = n0 + r0 + i;
        if (n < NN) {
            float rin = rsqrtf(fmaxf(g_indeg[n], 1.0f));
            float4 prev = *reinterpret_cast<float4*>(&out[(size_t)n * F + c0]);
            float4 o;
            o.x = (prev.x + acc[i][0]) * rin;
            o.y = (prev.y + acc[i][1]) * rin;
            o.z = (prev.z + acc[i][2]) * rin;
            o.w = (prev.w + acc[i][3]) * rin;
            *reinterpret_cast<float4*>(&out[(size_t)n * F + c0]) = o;
        }
    }
}

// ---------------- launcher ---------------------------------------------------
extern "C" void kernel_launch(void* const* d_in, const int* in_sizes, int n_in,
                              void* d_out, int out_size) {
    const float* feat  = (const float*)d_in[0];
    const int*   src   = (const int*)  d_in[1];
    const int*   dst   = (const int*)  d_in[2];
    const int*   eattr = (const int*)  d_in[3];
    const float* w1    = (const float*)d_in[4];
    const float* w2    = (const float*)d_in[5];
    const float* v     = (const float*)d_in[6];
    const float* bond  = (const float*)d_in[7];
    float* out = (float*)d_out;

    void *p_od, *p_id, *p_ls, *p_sg;
    cudaGetSymbolAddress(&p_od, g_outdeg);
    cudaGetSymbolAddress(&p_id, g_indeg);
    cudaGetSymbolAddress(&p_ls, g_logsum);
    cudaGetSymbolAddress(&p_sg, g_sign);

    cudaMemsetAsync(p_od, 0, NN * sizeof(float));
    cudaMemsetAsync(p_id, 0, NN * sizeof(float));
    cudaMemsetAsync(p_ls, 0, (size_t)NN * F * sizeof(float));
    cudaMemsetAsync(p_sg, 0, (size_t)NN * FG * sizeof(unsigned));
    cudaMemsetAsync(d_out, 0, (size_t)NN * F * sizeof(float));

    k_degree<<<(NE + 255) / 256, 256>>>(src, dst);
    k_node  <<<(NN + 63) / 64, 256>>>(feat, w1, w2);
    k_edge  <<<(NE + 7) / 8, 256>>>(src, dst, eattr, bond, out);
    k_final <<<(NN + 63) / 64, 256>>>(v, out);
}

// round 6
// speedup vs baseline: 1.1431x; 1.1431x over previous
#include <cuda_runtime.h>
#include <cuda_bf16.h>
#include <cstdint>

#define NN 100000
#define NE 800000
#define F  128
#define NT 782              // ceil(NN/128) node tiles
#define LDA 136             // smem row stride in bf16 elements (17 * uint4)
#define REG_BYTES (128 * LDA * 2)   // one 128x128(+pad) bf16 smem region = 34816 B

// ---------------- scratch ----------------------------------------------------
__device__ float    g_outdeg[NN];
__device__ float    g_indeg [NN];
__device__ float    g_hsum [(size_t)NN * F];
__device__ float    g_hprod[(size_t)NN * F];
__device__ float    g_logsum[(size_t)NN * F];
__device__ unsigned g_sign4[(size_t)NN * 4];
// weights pre-split to bf16 hi/lo in B^T layout: [out_col][k], plain row-major
__device__ __nv_bfloat16 g_w1h[F * F], g_w1l[F * F];
__device__ __nv_bfloat16 g_w2h[F * F], g_w2l[F * F];
__device__ __nv_bfloat16 g_vh [F * F], g_vl [F * F];

// ---------------- helpers ----------------------------------------------------
__device__ __forceinline__ uint32_t smem_to_u32(const void* p) {
    uint32_t a;
    asm("{ .reg .u64 t; cvta.to.shared.u64 t, %1; cvt.u32.u64 %0, t; }" : "=r"(a) : "l"(p));
    return a;
}

__device__ __forceinline__ void ldsm4(uint32_t& r0, uint32_t& r1, uint32_t& r2, uint32_t& r3,
                                      uint32_t addr) {
    asm volatile("ldmatrix.sync.aligned.m8n8.x4.shared.b16 {%0,%1,%2,%3}, [%4];"
                 : "=r"(r0), "=r"(r1), "=r"(r2), "=r"(r3) : "r"(addr));
}

__device__ __forceinline__ void mma_bf16(float* c, const uint32_t* a, const uint32_t* b) {
    asm volatile("mma.sync.aligned.m16n8k16.row.col.f32.bf16.bf16.f32 "
                 "{%0,%1,%2,%3}, {%4,%5,%6,%7}, {%8,%9}, {%0,%1,%2,%3};"
                 : "+f"(c[0]), "+f"(c[1]), "+f"(c[2]), "+f"(c[3])
                 : "r"(a[0]), "r"(a[1]), "r"(a[2]), "r"(a[3]), "r"(b[0]), "r"(b[1]));
}

// split a float4 into bf16 hi/lo packed words
__device__ __forceinline__ void split4(float4 x, uint2& H, uint2& L) {
    float xs[4] = {x.x, x.y, x.z, x.w};
    unsigned short h[4], l[4];
#pragma unroll
    for (int j = 0; j < 4; j++) {
        __nv_bfloat16 bh = __float2bfloat16(xs[j]);
        float r = xs[j] - __bfloat162float(bh);
        __nv_bfloat16 bl = __float2bfloat16(r);
        h[j] = __bfloat16_as_ushort(bh);
        l[j] = __bfloat16_as_ushort(bl);
    }
    H = make_uint2((uint32_t)h[0] | ((uint32_t)h[1] << 16),
                   (uint32_t)h[2] | ((uint32_t)h[3] << 16));
    L = make_uint2((uint32_t)l[0] | ((uint32_t)l[1] << 16),
                   (uint32_t)l[2] | ((uint32_t)l[3] << 16));
}

__device__ __forceinline__ void red_add_f4(float* p, float4 v) {
    asm volatile("red.global.add.v4.f32 [%0], {%1,%2,%3,%4};"
                 :: "l"(p), "f"(v.x), "f"(v.y), "f"(v.z), "f"(v.w) : "memory");
}

// copy a plain [128][128] bf16 global array into a stride-LDA smem region
__device__ __forceinline__ void copyB(__nv_bfloat16* dst, const __nv_bfloat16* src, int tid) {
    const uint4* s = (const uint4*)src;
    uint4* d = (uint4*)dst;
#pragma unroll
    for (int i = 0; i < 8; i++) {
        int idx = tid + i * 256;          // 0..2047
        int row = idx >> 4, col = idx & 15;
        d[row * 17 + col] = s[idx];
    }
}

// ---------------- K1: degrees ------------------------------------------------
__global__ void k_degree(const int* __restrict__ src, const int* __restrict__ dst) {
    int e = blockIdx.x * blockDim.x + threadIdx.x;
    if (e < NE) {
        atomicAdd(&g_outdeg[src[e]], 1.0f);
        atomicAdd(&g_indeg [dst[e]], 1.0f);
    }
}

// ---------------- K2: weights -> bf16 hi/lo B^T images ----------------------
__global__ void k_wprep(const float* __restrict__ w1, const float* __restrict__ w2,
                        const float* __restrict__ v) {
    int idx = blockIdx.x * 256 + threadIdx.x;   // 3 * 128 * 32 = 12288
    if (idx >= 12288) return;
    int mat = idx >> 12;
    int rem = idx & 4095;
    int o  = rem >> 5;
    int k0 = (rem & 31) * 4;
    const float* src = (mat == 0) ? w1 : (mat == 1) ? w2 : v;
    __nv_bfloat16* hi = (mat == 0) ? g_w1h : (mat == 1) ? g_w2h : g_vh;
    __nv_bfloat16* lo = (mat == 0) ? g_w1l : (mat == 1) ? g_w2l : g_vl;
    float4 x;
    x.x = src[(size_t)(k0 + 0) * F + o];
    x.y = src[(size_t)(k0 + 1) * F + o];
    x.z = src[(size_t)(k0 + 2) * F + o];
    x.w = src[(size_t)(k0 + 3) * F + o];
    uint2 H, L; split4(x, H, L);
    *reinterpret_cast<uint2*>(&hi[o * F + k0]) = H;
    *reinterpret_cast<uint2*>(&lo[o * F + k0]) = L;
}

// ---------------- K3: fused dual node GEMM via mma.sync ---------------------
// C[128 x 256] = A'[128 x 384] @ [W1' | W2'][384 x 256]  (3-pass bf16 split)
// 8 warps: warp_m = wid&1 (64 rows), warp_n = wid>>1 (64 cols)
__global__ __launch_bounds__(256, 1) void k_node_mma(const float* __restrict__ feat,
                                                     const float* __restrict__ w2full) {
    extern __shared__ __align__(16) unsigned char smem[];
    __nv_bfloat16* Ah = (__nv_bfloat16*)smem;
    __nv_bfloat16* Al = Ah + 128 * LDA;
    __nv_bfloat16* Bw[4];
    Bw[0] = Al    + 128 * LDA;   // w1 hi
    Bw[1] = Bw[0] + 128 * LDA;   // w1 lo
    Bw[2] = Bw[1] + 128 * LDA;   // w2 hi
    Bw[3] = Bw[2] + 128 * LDA;   // w2 lo

    const int tid = threadIdx.x, lane = tid & 31, wid = tid >> 5;
    const int bid = blockIdx.x;

    // fill A (convert feat -> scaled bf16 hi/lo)
    {
        int r = tid >> 1, hf = tid & 1;
        int n = bid * 128 + r;
        float s = 0.0f;
        if (n < NN) s = rsqrtf(fmaxf(g_outdeg[n], 1.0f));
#pragma unroll
        for (int q = 0; q < 16; q++) {
            int k0 = hf * 64 + q * 4;
            float4 x = make_float4(0.f, 0.f, 0.f, 0.f);
            if (n < NN) {
                x = *reinterpret_cast<const float4*>(&feat[(size_t)n * F + k0]);
                x.x *= s; x.y *= s; x.z *= s; x.w *= s;
            }
            uint2 H, L; split4(x, H, L);
            *reinterpret_cast<uint2*>(&Ah[r * LDA + k0]) = H;
            *reinterpret_cast<uint2*>(&Al[r * LDA + k0]) = L;
        }
    }
    copyB(Bw[0], g_w1h, tid);
    copyB(Bw[1], g_w1l, tid);
    copyB(Bw[2], g_w2h, tid);
    copyB(Bw[3], g_w2l, tid);
    __syncthreads();

    const int warp_m = wid & 1, warp_n = wid >> 1;
    const uint32_t sbase = smem_to_u32(smem);
    const uint32_t aAh = sbase, aAl = sbase + REG_BYTES;
    const int nl0 = (warp_n & 1) * 64;

    float c[4][8][4];
#pragma unroll
    for (int i = 0; i < 4; i++)
#pragma unroll
        for (int j = 0; j < 8; j++)
#pragma unroll
            for (int q = 0; q < 4; q++) c[i][j][q] = 0.f;

#pragma unroll 1
    for (int p = 0; p < 3; p++) {
        uint32_t Abase = (p == 2) ? aAl : aAh;
        uint32_t Bbase = sbase + (uint32_t)(2 + 2 * (warp_n >> 1) + (p == 1)) * REG_BYTES;
#pragma unroll
        for (int ks = 0; ks < 8; ks++) {
            int k0 = ks * 16;
            uint32_t a[4][4];
#pragma unroll
            for (int i = 0; i < 4; i++) {
                int row = warp_m * 64 + i * 16 + (lane & 15);
                ldsm4(a[i][0], a[i][1], a[i][2], a[i][3],
                      Abase + (uint32_t)(row * LDA + k0 + ((lane >> 4) << 3)) * 2);
            }
            uint32_t b[8][2];
#pragma unroll
            for (int jj = 0; jj < 4; jj++) {
                int o = nl0 + jj * 16 + (lane & 7) + ((lane >> 4) << 3);
                uint32_t r0, r1, r2, r3;
                ldsm4(r0, r1, r2, r3,
                      Bbase + (uint32_t)(o * LDA + k0 + (((lane >> 3) & 1) << 3)) * 2);
                b[jj * 2][0] = r0; b[jj * 2][1] = r1;
                b[jj * 2 + 1][0] = r2; b[jj * 2 + 1][1] = r3;
            }
#pragma unroll
            for (int i = 0; i < 4; i++)
#pragma unroll
                for (int j = 0; j < 8; j++)
                    mma_bf16(c[i][j], a[i], b[j]);
        }
    }

    // epilogue
    const int colbase = warp_n * 64;
#pragma unroll
    for (int i = 0; i < 4; i++) {
        int r0 = warp_m * 64 + i * 16 + (lane >> 2);
        int n0 = bid * 128 + r0;
        int n1 = n0 + 8;
#pragma unroll
        for (int j = 0; j < 8; j++) {
            int col = colbase + j * 8 + (lane & 3) * 2;
            if (col < 128) {
                if (n0 < NN)
                    *reinterpret_cast<float2*>(&g_hsum[(size_t)n0 * F + col]) =
                        make_float2(c[i][j][0], c[i][j][1]);
                if (n1 < NN)
                    *reinterpret_cast<float2*>(&g_hsum[(size_t)n1 * F + col]) =
                        make_float2(c[i][j][2], c[i][j][3]);
            } else {
                int c2 = col - 128;
                float2 bias = *reinterpret_cast<const float2*>(&w2full[(size_t)128 * F + c2]);
                if (n0 < NN)
                    *reinterpret_cast<float2*>(&g_hprod[(size_t)n0 * F + c2]) =
                        make_float2(tanhf(c[i][j][0] + bias.x), tanhf(c[i][j][1] + bias.y));
                if (n1 < NN)
                    *reinterpret_cast<float2*>(&g_hprod[(size_t)n1 * F + c2]) =
                        make_float2(tanhf(c[i][j][2] + bias.x), tanhf(c[i][j][3] + bias.y));
            }
        }
    }
}

// ---------------- K4: edge scatter ------------------------------------------
__global__ __launch_bounds__(256) void k_edge(const int* __restrict__ src,
                                              const int* __restrict__ dst,
                                              const int* __restrict__ eattr,
                                              const float* __restrict__ bond,
                                              float* __restrict__ out) {
    int e = blockIdx.x * 8 + (threadIdx.x >> 5);
    if (e >= NE) return;
    int g = threadIdx.x & 31;

    int s = __ldg(&src[e]);
    int d = __ldg(&dst[e]);
    int a = __ldg(&eattr[e]);

    float4 ew = __ldg(reinterpret_cast<const float4*>(bond) + (size_t)a * 32 + g);
    float4 hs = __ldg(reinterpret_cast<const float4*>(g_hsum)  + (size_t)s * 32 + g);
    float4 hp = __ldg(reinterpret_cast<const float4*>(g_hprod) + (size_t)s * 32 + g);

    float4 ms = make_float4(hs.x * ew.x, hs.y * ew.y, hs.z * ew.z, hs.w * ew.w);
    red_add_f4(out + (size_t)d * F + g * 4, ms);

    float4 mp = make_float4(hp.x * ew.x, hp.y * ew.y, hp.z * ew.z, hp.w * ew.w);
    float4 lg;
    lg.x = __logf(fabsf(mp.x));
    lg.y = __logf(fabsf(mp.y));
    lg.z = __logf(fabsf(mp.z));
    lg.w = __logf(fabsf(mp.w));
    red_add_f4(&g_logsum[(size_t)d * F + g * 4], lg);

    unsigned m =  ((__float_as_uint(mp.x) >> 31) & 1u)
               | (((__float_as_uint(mp.y) >> 31) & 1u) << 1)
               | (((__float_as_uint(mp.z) >> 31) & 1u) << 2)
               | (((__float_as_uint(mp.w) >> 31) & 1u) << 3);
    unsigned sub = 0xFFu << ((g >> 3) * 8);
    unsigned r = __reduce_xor_sync(sub, m << ((g & 7) * 4));
    if ((g & 7) == 0 && r)
        atomicXor(&g_sign4[(size_t)d * 4 + (g >> 3)], r);
}

// ---------------- K5: final GEMM (hp @ v) + epilogue ------------------------
// A = sign*exp(logsum) built in-kernel; C[128x128]; 8 warps: warp tile 64x32
__global__ __launch_bounds__(256, 1) void k_final_mma(float* __restrict__ out) {
    extern __shared__ __align__(16) unsigned char smem[];
    __nv_bfloat16* Ah = (__nv_bfloat16*)smem;
    __nv_bfloat16* Al = Ah + 128 * LDA;
    __nv_bfloat16* Bh = Al + 128 * LDA;
    __nv_bfloat16* Bl = Bh + 128 * LDA;

    const int tid = threadIdx.x, lane = tid & 31, wid = tid >> 5;
    const int bid = blockIdx.x;

    // fill A: hp = sign * exp(logsum), split to bf16 hi/lo
    {
        int r = tid >> 1, hf = tid & 1;
        int n = bid * 128 + r;
        unsigned w0 = 0, w1v = 0;
        if (n < NN) {
            w0  = g_sign4[(size_t)n * 4 + 2 * hf];
            w1v = g_sign4[(size_t)n * 4 + 2 * hf + 1];
        }
#pragma unroll
        for (int q = 0; q < 16; q++) {
            int k0 = hf * 64 + q * 4;
            float4 x = make_float4(0.f, 0.f, 0.f, 0.f);
            if (n < NN) {
                float4 lv = *reinterpret_cast<const float4*>(&g_logsum[(size_t)n * F + k0]);
                unsigned w = (q < 8) ? w0 : w1v;
                int b = k0 & 31;
                x.x = __expf(lv.x); if ((w >> (b + 0)) & 1u) x.x = -x.x;
                x.y = __expf(lv.y); if ((w >> (b + 1)) & 1u) x.y = -x.y;
                x.z = __expf(lv.z); if ((w >> (b + 2)) & 1u) x.z = -x.z;
                x.w = __expf(lv.w); if ((w >> (b + 3)) & 1u) x.w = -x.w;
            }
            uint2 H, L; split4(x, H, L);
            *reinterpret_cast<uint2*>(&Ah[r * LDA + k0]) = H;
            *reinterpret_cast<uint2*>(&Al[r * LDA + k0]) = L;
        }
    }
    copyB(Bh, g_vh, tid);
    copyB(Bl, g_vl, tid);
    __syncthreads();

    const int warp_m = wid & 1, warp_n = wid >> 1;     // 2 x 4, warp tile 64x32
    const uint32_t sbase = smem_to_u32(smem);
    const uint32_t aAh = sbase, aAl = sbase + REG_BYTES;
    const uint32_t aBh = sbase + 2 * REG_BYTES, aBl = sbase + 3 * REG_BYTES;
    const int nl0 = warp_n * 32;

    float c[4][4][4];
#pragma unroll
    for (int i = 0; i < 4; i++)
#pragma unroll
        for (int j = 0; j < 4; j++)
#pragma unroll
            for (int q = 0; q < 4; q++) c[i][j][q] = 0.f;

#pragma unroll 1
    for (int p = 0; p < 3; p++) {
        uint32_t Abase = (p == 2) ? aAl : aAh;
        uint32_t Bbase = (p == 1) ? aBl : aBh;
#pragma unroll
        for (int ks = 0; ks < 8; ks++) {
            int k0 = ks * 16;
            uint32_t a[4][4];
#pragma unroll
            for (int i = 0; i < 4; i++) {
                int row = warp_m * 64 + i * 16 + (lane & 15);
                ldsm4(a[i][0], a[i][1], a[i][2], a[i][3],
                      Abase + (uint32_t)(row * LDA + k0 + ((lane >> 4) << 3)) * 2);
            }
            uint32_t b[4][2];
#pragma unroll
            for (int jj = 0; jj < 2; jj++) {
                int o = nl0 + jj * 16 + (lane & 7) + ((lane >> 4) << 3);
                uint32_t r0, r1, r2, r3;
                ldsm4(r0, r1, r2, r3,
                      Bbase + (uint32_t)(o * LDA + k0 + (((lane >> 3) & 1) << 3)) * 2);
                b[jj * 2][0] = r0; b[jj * 2][1] = r1;
                b[jj * 2 + 1][0] = r2; b[jj * 2 + 1][1] = r3;
            }
#pragma unroll
            for (int i = 0; i < 4; i++)
#pragma unroll
                for (int j = 0; j < 4; j++)
                    mma_bf16(c[i][j], a[i], b[j]);
        }
    }

    // epilogue: out = (out + C) * indeg^-1/2
#pragma unroll
    for (int i = 0; i < 4; i++) {
        int r0 = warp_m * 64 + i * 16 + (lane >> 2);
        int n0 = bid * 128 + r0;
        int n1 = n0 + 8;
        float rin0 = (n0 < NN) ? rsqrtf(fmaxf(g_indeg[n0], 1.0f)) : 0.f;
        float rin1 = (n1 < NN) ? rsqrtf(fmaxf(g_indeg[n1], 1.0f)) : 0.f;
#pragma unroll
        for (int j = 0; j < 4; j++) {
            int col = nl0 + j * 8 + (lane & 3) * 2;
            if (n0 < NN) {
                float2* p = reinterpret_cast<float2*>(&out[(size_t)n0 * F + col]);
                float2 prev = *p;
                *p = make_float2((prev.x + c[i][j][0]) * rin0,
                                 (prev.y + c[i][j][1]) * rin0);
            }
            if (n1 < NN) {
                float2* p = reinterpret_cast<float2*>(&out[(size_t)n1 * F + col]);
                float2 prev = *p;
                *p = make_float2((prev.x + c[i][j][2]) * rin1,
                                 (prev.y + c[i][j][3]) * rin1);
            }
        }
    }
}

// ---------------- launcher ---------------------------------------------------
#define SMEM_NODE (6 * REG_BYTES)
#define SMEM_FIN  (4 * REG_BYTES)

extern "C" void kernel_launch(void* const* d_in, const int* in_sizes, int n_in,
                              void* d_out, int out_size) {
    const float* feat  = (const float*)d_in[0];
    const int*   src   = (const int*)  d_in[1];
    const int*   dst   = (const int*)  d_in[2];
    const int*   eattr = (const int*)  d_in[3];
    const float* w1    = (const float*)d_in[4];
    const float* w2    = (const float*)d_in[5];
    const float* v     = (const float*)d_in[6];
    const float* bond  = (const float*)d_in[7];
    float* out = (float*)d_out;

    cudaFuncSetAttribute(k_node_mma,  cudaFuncAttributeMaxDynamicSharedMemorySize, SMEM_NODE);
    cudaFuncSetAttribute(k_final_mma, cudaFuncAttributeMaxDynamicSharedMemorySize, SMEM_FIN);

    void *p_od, *p_id, *p_ls, *p_sg;
    cudaGetSymbolAddress(&p_od, g_outdeg);
    cudaGetSymbolAddress(&p_id, g_indeg);
    cudaGetSymbolAddress(&p_ls, g_logsum);
    cudaGetSymbolAddress(&p_sg, g_sign4);

    cudaMemsetAsync(p_od, 0, NN * sizeof(float));
    cudaMemsetAsync(p_id, 0, NN * sizeof(float));
    cudaMemsetAsync(p_ls, 0, (size_t)NN * F * sizeof(float));
    cudaMemsetAsync(p_sg, 0, (size_t)NN * 4 * sizeof(unsigned));
    cudaMemsetAsync(d_out, 0, (size_t)NN * F * sizeof(float));

    k_degree   <<<(NE + 255) / 256, 256>>>(src, dst);
    k_wprep    <<<48, 256>>>(w1, w2, v);
    k_node_mma <<<NT, 256, SMEM_NODE>>>(feat, w2);
    k_edge     <<<(NE + 7) / 8, 256>>>(src, dst, eattr, bond, out);
    k_final_mma<<<NT, 256, SMEM_FIN>>>(out);
}

// round 7
// speedup vs baseline: 1.5801x; 1.3823x over previous
#include <cuda_runtime.h>
#include <cuda_bf16.h>
#include <cstdint>

#define NN 100000
#define NE 800000
#define F  128
#define NT 782              // ceil(NN/128) node tiles
#define NB 391              // ceil(NN/256) scan blocks
#define LDA 136             // smem row stride in bf16 elements
#define REG_BYTES (128 * LDA * 2)

// ---------------- scratch ----------------------------------------------------
__device__ int      g_indeg_i [NN];
__device__ int      g_outdeg_i[NN];
__device__ int      g_rowstart[NN];
__device__ int      g_cursor  [NN];
__device__ float    g_rin     [NN];
__device__ int      g_blksum  [512];
__device__ unsigned g_csr     [NE];
__device__ float    g_hsum [(size_t)NN * F];
__device__ float    g_hprod[(size_t)NN * F];
__device__ float    g_hp   [(size_t)NN * F];
__device__ __nv_bfloat16 g_w1h[F * F], g_w1l[F * F];
__device__ __nv_bfloat16 g_w2h[F * F], g_w2l[F * F];
__device__ __nv_bfloat16 g_vh [F * F], g_vl [F * F];

// ---------------- helpers ----------------------------------------------------
__device__ __forceinline__ uint32_t smem_to_u32(const void* p) {
    uint32_t a;
    asm("{ .reg .u64 t; cvta.to.shared.u64 t, %1; cvt.u32.u64 %0, t; }" : "=r"(a) : "l"(p));
    return a;
}

__device__ __forceinline__ void ldsm4(uint32_t& r0, uint32_t& r1, uint32_t& r2, uint32_t& r3,
                                      uint32_t addr) {
    asm volatile("ldmatrix.sync.aligned.m8n8.x4.shared.b16 {%0,%1,%2,%3}, [%4];"
                 : "=r"(r0), "=r"(r1), "=r"(r2), "=r"(r3) : "r"(addr));
}

__device__ __forceinline__ void mma_bf16(float* c, const uint32_t* a, const uint32_t* b) {
    asm volatile("mma.sync.aligned.m16n8k16.row.col.f32.bf16.bf16.f32 "
                 "{%0,%1,%2,%3}, {%4,%5,%6,%7}, {%8,%9}, {%0,%1,%2,%3};"
                 : "+f"(c[0]), "+f"(c[1]), "+f"(c[2]), "+f"(c[3])
                 : "r"(a[0]), "r"(a[1]), "r"(a[2]), "r"(a[3]), "r"(b[0]), "r"(b[1]));
}

__device__ __forceinline__ void split4(float4 x, uint2& H, uint2& L) {
    float xs[4] = {x.x, x.y, x.z, x.w};
    unsigned short h[4], l[4];
#pragma unroll
    for (int j = 0; j < 4; j++) {
        __nv_bfloat16 bh = __float2bfloat16(xs[j]);
        float r = xs[j] - __bfloat162float(bh);
        __nv_bfloat16 bl = __float2bfloat16(r);
        h[j] = __bfloat16_as_ushort(bh);
        l[j] = __bfloat16_as_ushort(bl);
    }
    H = make_uint2((uint32_t)h[0] | ((uint32_t)h[1] << 16),
                   (uint32_t)h[2] | ((uint32_t)h[3] << 16));
    L = make_uint2((uint32_t)l[0] | ((uint32_t)l[1] << 16),
                   (uint32_t)l[2] | ((uint32_t)l[3] << 16));
}

__device__ __forceinline__ void copyB(__nv_bfloat16* dst, const __nv_bfloat16* src, int tid) {
    const uint4* s = (const uint4*)src;
    uint4* d = (uint4*)dst;
#pragma unroll
    for (int i = 0; i < 8; i++) {
        int idx = tid + i * 256;
        int row = idx >> 4, col = idx & 15;
        d[row * 17 + col] = s[idx];
    }
}

// ---------------- CSR build --------------------------------------------------
__global__ void k_count(const int* __restrict__ src, const int* __restrict__ dst) {
    int e = blockIdx.x * blockDim.x + threadIdx.x;
    if (e < NE) {
        atomicAdd(&g_indeg_i [dst[e]], 1);
        atomicAdd(&g_outdeg_i[src[e]], 1);
    }
}

__global__ void k_scan1() {
    __shared__ int swarp[8];
    int t = threadIdx.x, b = blockIdx.x;
    int i = b * 256 + t;
    int v = (i < NN) ? g_indeg_i[i] : 0;
    int x = v;
    int lane = t & 31, w = t >> 5;
#pragma unroll
    for (int o = 1; o < 32; o <<= 1) {
        int y = __shfl_up_sync(0xffffffffu, x, o);
        if (lane >= o) x += y;
    }
    if (lane == 31) swarp[w] = x;
    __syncthreads();
    if (w == 0) {
        int s = (lane < 8) ? swarp[lane] : 0;
#pragma unroll
        for (int o = 1; o < 8; o <<= 1) {
            int y = __shfl_up_sync(0xffffffffu, s, o);
            if (lane >= o) s += y;
        }
        if (lane < 8) swarp[lane] = s;
    }
    __syncthreads();
    int off = (w > 0) ? swarp[w - 1] : 0;
    if (i < NN) g_rowstart[i] = x - v + off;
    if (t == 255) g_blksum[b] = x + off;
}

__global__ void k_scan2() {
    __shared__ int swarp[16];
    int t = threadIdx.x;
    int v = (t < NB) ? g_blksum[t] : 0;
    int x = v;
    int lane = t & 31, w = t >> 5;
#pragma unroll
    for (int o = 1; o < 32; o <<= 1) {
        int y = __shfl_up_sync(0xffffffffu, x, o);
        if (lane >= o) x += y;
    }
    if (lane == 31) swarp[w] = x;
    __syncthreads();
    if (w == 0) {
        int s = (lane < 16) ? swarp[lane] : 0;
#pragma unroll
        for (int o = 1; o < 16; o <<= 1) {
            int y = __shfl_up_sync(0xffffffffu, s, o);
            if (lane >= o) s += y;
        }
        if (lane < 16) swarp[lane] = s;
    }
    __syncthreads();
    int off = (w > 0) ? swarp[w - 1] : 0;
    if (t < NB) g_blksum[t] = x - v + off;    // exclusive
}

__global__ void k_scan3() {
    int i = blockIdx.x * 256 + threadIdx.x;
    if (i < NN) {
        int r = g_rowstart[i] + g_blksum[blockIdx.x];
        g_rowstart[i] = r;
        g_cursor[i]   = r;
        g_rin[i]      = rsqrtf(fmaxf((float)g_indeg_i[i], 1.0f));
    }
}

__global__ void k_scatter(const int* __restrict__ src, const int* __restrict__ dst,
                          const int* __restrict__ eattr) {
    int e = blockIdx.x * blockDim.x + threadIdx.x;
    if (e < NE) {
        int d = dst[e];
        int pos = atomicAdd(&g_cursor[d], 1);
        g_csr[pos] = (unsigned)src[e] | ((unsigned)eattr[e] << 17);
    }
}

// ---------------- weights -> bf16 hi/lo B^T images --------------------------
__global__ void k_wprep(const float* __restrict__ w1, const float* __restrict__ w2,
                        const float* __restrict__ v) {
    int idx = blockIdx.x * 256 + threadIdx.x;
    if (idx >= 12288) return;
    int mat = idx >> 12;
    int rem = idx & 4095;
    int o  = rem >> 5;
    int k0 = (rem & 31) * 4;
    const float* src = (mat == 0) ? w1 : (mat == 1) ? w2 : v;
    __nv_bfloat16* hi = (mat == 0) ? g_w1h : (mat == 1) ? g_w2h : g_vh;
    __nv_bfloat16* lo = (mat == 0) ? g_w1l : (mat == 1) ? g_w2l : g_vl;
    float4 x;
    x.x = src[(size_t)(k0 + 0) * F + o];
    x.y = src[(size_t)(k0 + 1) * F + o];
    x.z = src[(size_t)(k0 + 2) * F + o];
    x.w = src[(size_t)(k0 + 3) * F + o];
    uint2 H, L; split4(x, H, L);
    *reinterpret_cast<uint2*>(&hi[o * F + k0]) = H;
    *reinterpret_cast<uint2*>(&lo[o * F + k0]) = L;
}

// ---------------- fused dual node GEMM via mma.sync -------------------------
__global__ __launch_bounds__(256, 1) void k_node_mma(const float* __restrict__ feat,
                                                     const float* __restrict__ w2full) {
    extern __shared__ __align__(16) unsigned char smem[];
    __nv_bfloat16* Ah = (__nv_bfloat16*)smem;
    __nv_bfloat16* Al = Ah + 128 * LDA;
    __nv_bfloat16* Bw[4];
    Bw[0] = Al    + 128 * LDA;
    Bw[1] = Bw[0] + 128 * LDA;
    Bw[2] = Bw[1] + 128 * LDA;
    Bw[3] = Bw[2] + 128 * LDA;

    const int tid = threadIdx.x, lane = tid & 31, wid = tid >> 5;
    const int bid = blockIdx.x;

    {
        int r = tid >> 1, hf = tid & 1;
        int n = bid * 128 + r;
        float s = 0.0f;
        if (n < NN) s = rsqrtf(fmaxf((float)g_outdeg_i[n], 1.0f));
#pragma unroll
        for (int q = 0; q < 16; q++) {
            int k0 = hf * 64 + q * 4;
            float4 x = make_float4(0.f, 0.f, 0.f, 0.f);
            if (n < NN) {
                x = *reinterpret_cast<const float4*>(&feat[(size_t)n * F + k0]);
                x.x *= s; x.y *= s; x.z *= s; x.w *= s;
            }
            uint2 H, L; split4(x, H, L);
            *reinterpret_cast<uint2*>(&Ah[r * LDA + k0]) = H;
            *reinterpret_cast<uint2*>(&Al[r * LDA + k0]) = L;
        }
    }
    copyB(Bw[0], g_w1h, tid);
    copyB(Bw[1], g_w1l, tid);
    copyB(Bw[2], g_w2h, tid);
    copyB(Bw[3], g_w2l, tid);
    __syncthreads();

    const int warp_m = wid & 1, warp_n = wid >> 1;
    const uint32_t sbase = smem_to_u32(smem);
    const uint32_t aAh = sbase, aAl = sbase + REG_BYTES;
    const int nl0 = (warp_n & 1) * 64;

    float c[4][8][4];
#pragma unroll
    for (int i = 0; i < 4; i++)
#pragma unroll
        for (int j = 0; j < 8; j++)
#pragma unroll
            for (int q = 0; q < 4; q++) c[i][j][q] = 0.f;

#pragma unroll 1
    for (int p = 0; p < 3; p++) {
        uint32_t Abase = (p == 2) ? aAl : aAh;
        uint32_t Bbase = sbase + (uint32_t)(2 + 2 * (warp_n >> 1) + (p == 1)) * REG_BYTES;
#pragma unroll
        for (int ks = 0; ks < 8; ks++) {
            int k0 = ks * 16;
            uint32_t a[4][4];
#pragma unroll
            for (int i = 0; i < 4; i++) {
                int row = warp_m * 64 + i * 16 + (lane & 15);
                ldsm4(a[i][0], a[i][1], a[i][2], a[i][3],
                      Abase + (uint32_t)(row * LDA + k0 + ((lane >> 4) << 3)) * 2);
            }
            uint32_t b[8][2];
#pragma unroll
            for (int jj = 0; jj < 4; jj++) {
                int o = nl0 + jj * 16 + (lane & 7) + ((lane >> 4) << 3);
                uint32_t r0, r1, r2, r3;
                ldsm4(r0, r1, r2, r3,
                      Bbase + (uint32_t)(o * LDA + k0 + (((lane >> 3) & 1) << 3)) * 2);
                b[jj * 2][0] = r0; b[jj * 2][1] = r1;
                b[jj * 2 + 1][0] = r2; b[jj * 2 + 1][1] = r3;
            }
#pragma unroll
            for (int i = 0; i < 4; i++)
#pragma unroll
                for (int j = 0; j < 8; j++)
                    mma_bf16(c[i][j], a[i], b[j]);
        }
    }

    const int colbase = warp_n * 64;
#pragma unroll
    for (int i = 0; i < 4; i++) {
        int r0 = warp_m * 64 + i * 16 + (lane >> 2);
        int n0 = bid * 128 + r0;
        int n1 = n0 + 8;
#pragma unroll
        for (int j = 0; j < 8; j++) {
            int col = colbase + j * 8 + (lane & 3) * 2;
            if (col < 128) {
                if (n0 < NN)
                    *reinterpret_cast<float2*>(&g_hsum[(size_t)n0 * F + col]) =
                        make_float2(c[i][j][0], c[i][j][1]);
                if (n1 < NN)
                    *reinterpret_cast<float2*>(&g_hsum[(size_t)n1 * F + col]) =
                        make_float2(c[i][j][2], c[i][j][3]);
            } else {
                int c2 = col - 128;
                float2 bias = *reinterpret_cast<const float2*>(&w2full[(size_t)128 * F + c2]);
                if (n0 < NN)
                    *reinterpret_cast<float2*>(&g_hprod[(size_t)n0 * F + c2]) =
                        make_float2(tanhf(c[i][j][0] + bias.x), tanhf(c[i][j][1] + bias.y));
                if (n1 < NN)
                    *reinterpret_cast<float2*>(&g_hprod[(size_t)n1 * F + c2]) =
                        make_float2(tanhf(c[i][j][2] + bias.x), tanhf(c[i][j][3] + bias.y));
            }
        }
    }
}

// ---------------- gather: per-dst register accumulation ---------------------
__global__ __launch_bounds__(256) void k_gather(const float* __restrict__ bond,
                                                float* __restrict__ out) {
    int n = blockIdx.x * 8 + (threadIdx.x >> 5);
    if (n >= NN) return;
    int g = threadIdx.x & 31;

    int base = g_rowstart[n];
    int deg  = g_indeg_i[n];

    const float4* hs4 = (const float4*)g_hsum;
    const float4* hp4 = (const float4*)g_hprod;
    const float4* bd4 = (const float4*)bond;

    float4 as = make_float4(0.f, 0.f, 0.f, 0.f);
    float4 al = make_float4(0.f, 0.f, 0.f, 0.f);
    unsigned sg = 0;

    int i = 0;
    for (; i + 2 <= deg; i += 2) {
        unsigned r0 = __ldg(&g_csr[base + i]);
        unsigned r1 = __ldg(&g_csr[base + i + 1]);
        int s0 = r0 & 0x1FFFF, a0 = r0 >> 17;
        int s1 = r1 & 0x1FFFF, a1 = r1 >> 17;
        float4 e0 = __ldg(bd4 + (size_t)a0 * 32 + g);
        float4 e1 = __ldg(bd4 + (size_t)a1 * 32 + g);
        float4 h0 = __ldg(hs4 + (size_t)s0 * 32 + g);
        float4 h1 = __ldg(hs4 + (size_t)s1 * 32 + g);
        float4 p0 = __ldg(hp4 + (size_t)s0 * 32 + g);
        float4 p1 = __ldg(hp4 + (size_t)s1 * 32 + g);

        as.x += h0.x * e0.x + h1.x * e1.x;
        as.y += h0.y * e0.y + h1.y * e1.y;
        as.z += h0.z * e0.z + h1.z * e1.z;
        as.w += h0.w * e0.w + h1.w * e1.w;

        float4 m0 = make_float4(p0.x * e0.x, p0.y * e0.y, p0.z * e0.z, p0.w * e0.w);
        float4 m1 = make_float4(p1.x * e1.x, p1.y * e1.y, p1.z * e1.z, p1.w * e1.w);
        al.x += __logf(fabsf(m0.x)) + __logf(fabsf(m1.x));
        al.y += __logf(fabsf(m0.y)) + __logf(fabsf(m1.y));
        al.z += __logf(fabsf(m0.z)) + __logf(fabsf(m1.z));
        al.w += __logf(fabsf(m0.w)) + __logf(fabsf(m1.w));
        sg ^=  ((__float_as_uint(m0.x) >> 31) & 1u)
            | (((__float_as_uint(m0.y) >> 31) & 1u) << 1)
            | (((__float_as_uint(m0.z) >> 31) & 1u) << 2)
            | (((__float_as_uint(m0.w) >> 31) & 1u) << 3);
        sg ^=  ((__float_as_uint(m1.x) >> 31) & 1u)
            | (((__float_as_uint(m1.y) >> 31) & 1u) << 1)
            | (((__float_as_uint(m1.z) >> 31) & 1u) << 2)
            | (((__float_as_uint(m1.w) >> 31) & 1u) << 3);
    }
    if (i < deg) {
        unsigned r0 = __ldg(&g_csr[base + i]);
        int s0 = r0 & 0x1FFFF, a0 = r0 >> 17;
        float4 e0 = __ldg(bd4 + (size_t)a0 * 32 + g);
        float4 h0 = __ldg(hs4 + (size_t)s0 * 32 + g);
        float4 p0 = __ldg(hp4 + (size_t)s0 * 32 + g);
        as.x += h0.x * e0.x; as.y += h0.y * e0.y;
        as.z += h0.z * e0.z; as.w += h0.w * e0.w;
        float4 m0 = make_float4(p0.x * e0.x, p0.y * e0.y, p0.z * e0.z, p0.w * e0.w);
        al.x += __logf(fabsf(m0.x));
        al.y += __logf(fabsf(m0.y));
        al.z += __logf(fabsf(m0.z));
        al.w += __logf(fabsf(m0.w));
        sg ^=  ((__float_as_uint(m0.x) >> 31) & 1u)
            | (((__float_as_uint(m0.y) >> 31) & 1u) << 1)
            | (((__float_as_uint(m0.z) >> 31) & 1u) << 2)
            | (((__float_as_uint(m0.w) >> 31) & 1u) << 3);
    }

    *reinterpret_cast<float4*>(&out[(size_t)n * F + g * 4]) = as;

    float4 hp;
    hp.x = __expf(al.x); if (sg & 1u) hp.x = -hp.x;
    hp.y = __expf(al.y); if (sg & 2u) hp.y = -hp.y;
    hp.z = __expf(al.z); if (sg & 4u) hp.z = -hp.z;
    hp.w = __expf(al.w); if (sg & 8u) hp.w = -hp.w;
    *reinterpret_cast<float4*>(&g_hp[(size_t)n * F + g * 4]) = hp;
}

// ---------------- final GEMM (hp @ v) + epilogue ----------------------------
__global__ __launch_bounds__(256, 1) void k_final_mma(float* __restrict__ out) {
    extern __shared__ __align__(16) unsigned char smem[];
    __nv_bfloat16* Ah = (__nv_bfloat16*)smem;
    __nv_bfloat16* Al = Ah + 128 * LDA;
    __nv_bfloat16* Bh = Al + 128 * LDA;
    __nv_bfloat16* Bl = Bh + 128 * LDA;

    const int tid = threadIdx.x, lane = tid & 31, wid = tid >> 5;
    const int bid = blockIdx.x;

    {
        int r = tid >> 1, hf = tid & 1;
        int n = bid * 128 + r;
#pragma unroll
        for (int q = 0; q < 16; q++) {
            int k0 = hf * 64 + q * 4;
            float4 x = make_float4(0.f, 0.f, 0.f, 0.f);
            if (n < NN)
                x = *reinterpret_cast<const float4*>(&g_hp[(size_t)n * F + k0]);
            uint2 H, L; split4(x, H, L);
            *reinterpret_cast<uint2*>(&Ah[r * LDA + k0]) = H;
            *reinterpret_cast<uint2*>(&Al[r * LDA + k0]) = L;
        }
    }
    copyB(Bh, g_vh, tid);
    copyB(Bl, g_vl, tid);
    __syncthreads();

    const int warp_m = wid & 1, warp_n = wid >> 1;
    const uint32_t sbase = smem_to_u32(smem);
    const uint32_t aAh = sbase, aAl = sbase + REG_BYTES;
    const uint32_t aBh = sbase + 2 * REG_BYTES, aBl = sbase + 3 * REG_BYTES;
    const int nl0 = warp_n * 32;

    float c[4][4][4];
#pragma unroll
    for (int i = 0; i < 4; i++)
#pragma unroll
        for (int j = 0; j < 4; j++)
#pragma unroll
            for (int q = 0; q < 4; q++) c[i][j][q] = 0.f;

#pragma unroll 1
    for (int p = 0; p < 3; p++) {
        uint32_t Abase = (p == 2) ? aAl : aAh;
        uint32_t Bbase = (p == 1) ? aBl : aBh;
#pragma unroll
        for (int ks = 0; ks < 8; ks++) {
            int k0 = ks * 16;
            uint32_t a[4][4];
#pragma unroll
            for (int i = 0; i < 4; i++) {
                int row = warp_m * 64 + i * 16 + (lane & 15);
                ldsm4(a[i][0], a[i][1], a[i][2], a[i][3],
                      Abase + (uint32_t)(row * LDA + k0 + ((lane >> 4) << 3)) * 2);
            }
            uint32_t b[4][2];
#pragma unroll
            for (int jj = 0; jj < 2; jj++) {
                int o = nl0 + jj * 16 + (lane & 7) + ((lane >> 4) << 3);
                uint32_t r0, r1, r2, r3;
                ldsm4(r0, r1, r2, r3,
                      Bbase + (uint32_t)(o * LDA + k0 + (((lane >> 3) & 1) << 3)) * 2);
                b[jj * 2][0] = r0; b[jj * 2][1] = r1;
                b[jj * 2 + 1][0] = r2; b[jj * 2 + 1][1] = r3;
            }
#pragma unroll
            for (int i = 0; i < 4; i++)
#pragma unroll
                for (int j = 0; j < 4; j++)
                    mma_bf16(c[i][j], a[i], b[j]);
        }
    }

#pragma unroll
    for (int i = 0; i < 4; i++) {
        int r0 = warp_m * 64 + i * 16 + (lane >> 2);
        int n0 = bid * 128 + r0;
        int n1 = n0 + 8;
        float rin0 = (n0 < NN) ? g_rin[n0] : 0.f;
        float rin1 = (n1 < NN) ? g_rin[n1] : 0.f;
#pragma unroll
        for (int j = 0; j < 4; j++) {
            int col = nl0 + j * 8 + (lane & 3) * 2;
            if (n0 < NN) {
                float2* p = reinterpret_cast<float2*>(&out[(size_t)n0 * F + col]);
                float2 prev = *p;
                *p = make_float2((prev.x + c[i][j][0]) * rin0,
                                 (prev.y + c[i][j][1]) * rin0);
            }
            if (n1 < NN) {
                float2* p = reinterpret_cast<float2*>(&out[(size_t)n1 * F + col]);
                float2 prev = *p;
                *p = make_float2((prev.x + c[i][j][2]) * rin1,
                                 (prev.y + c[i][j][3]) * rin1);
            }
        }
    }
}

// ---------------- launcher ---------------------------------------------------
#define SMEM_NODE (6 * REG_BYTES)
#define SMEM_FIN  (4 * REG_BYTES)

extern "C" void kernel_launch(void* const* d_in, const int* in_sizes, int n_in,
                              void* d_out, int out_size) {
    const float* feat  = (const float*)d_in[0];
    const int*   src   = (const int*)  d_in[1];
    const int*   dst   = (const int*)  d_in[2];
    const int*   eattr = (const int*)  d_in[3];
    const float* w1    = (const float*)d_in[4];
    const float* w2    = (const float*)d_in[5];
    const float* v     = (const float*)d_in[6];
    const float* bond  = (const float*)d_in[7];
    float* out = (float*)d_out;

    cudaFuncSetAttribute(k_node_mma,  cudaFuncAttributeMaxDynamicSharedMemorySize, SMEM_NODE);
    cudaFuncSetAttribute(k_final_mma, cudaFuncAttributeMaxDynamicSharedMemorySize, SMEM_FIN);

    void *p_id, *p_od;
    cudaGetSymbolAddress(&p_id, g_indeg_i);
    cudaGetSymbolAddress(&p_od, g_outdeg_i);
    cudaMemsetAsync(p_id, 0, NN * sizeof(int));
    cudaMemsetAsync(p_od, 0, NN * sizeof(int));

    k_count    <<<(NE + 255) / 256, 256>>>(src, dst);
    k_scan1    <<<NB, 256>>>();
    k_scan2    <<<1, 512>>>();
    k_scan3    <<<NB, 256>>>();
    k_wprep    <<<48, 256>>>(w1, w2, v);
    k_scatter  <<<(NE + 255) / 256, 256>>>(src, dst, eattr);
    k_node_mma <<<NT, 256, SMEM_NODE>>>(feat, w2);
    k_gather   <<<(NN + 7) / 8, 256>>>(bond, out);
    k_final_mma<<<NT, 256, SMEM_FIN>>>(out);
}